// round 15
// baseline (speedup 1.0000x reference)
#include <cuda_runtime.h>
#include <math_constants.h>

#define NCLS    19
#define NBINS   15
#define HW      (512 * 1024)          // 2^19 pixels per image
#define NPIX    (4 * HW)              // 2,097,152
#define NCELLS  (NCLS * NBINS)        // 285
#define NT      512
#define GX      111                   // blocks per image; 111*4 = 444 = 3/SM
#define GRIDB   (GX * 4)
#define PPB     (NT / 4)              // 128 pixels per block-iteration
#define STRIDE  (GX * PPB)            // 14,208 pixels

// g_hist[c*15+b] = sum of 15*(p - [label==c]) over pixels with bin(p_c)=b.
// sce = sum(|g_hist|) / (15*C*N).  Invariant: zero at entry; last block resets.
__device__ float    g_hist[NCELLS];
__device__ unsigned g_count;

__global__ __launch_bounds__(NT, 3)
void ece_fused(const float* __restrict__ logits,
               const int*   __restrict__ labels,
               float*       __restrict__ out) {
    __shared__ float s_hist[NCELLS];
    __shared__ bool  s_last;
    for (int i = threadIdx.x; i < NCELLS; i += NT) s_hist[i] = 0.f;
    __syncthreads();

    const unsigned sbase = (unsigned)__cvta_generic_to_shared(s_hist);
    const int g  = threadIdx.x & 3;       // class-group within the pixel quad
    const int q  = threadIdx.x >> 2;      // pixel slot within block
    const int c0 = g * 5;                 // first class of this group (g=3 has 4)

    const float* imgbase = logits + (size_t)blockIdx.y * (NCLS * HW);
    const int*   labbase = labels + (size_t)blockIdx.y * HW;

    // Slots 0-3 load at pbase + i*HW (compile-time immediate offsets).
    // Slot 4 is remapped min(c0+4, 18): for g==3 it duplicates class 18.
    const float* pbase = imgbase + (size_t)c0 * HW;
    const float* p4    = imgbase + (size_t)min(c0 + 4, NCLS - 1) * HW;
    const float  dead  = (c0 + 4 < NCLS) ? 0.f : 1.f;   // S compensation
    const float  thr4  = (c0 + 4 < NCLS) ? 2.f : CUDART_INF_F; // slot-4 red off
    // Red-address base for this thread's class group (slot offset is immediate).
    const unsigned cb0 = sbase + (unsigned)((c0 * NBINS - 1) << 2);

    // Cumulative register bins per owned class: a0 = sum v over t<=1, a1 over t<=2.
    float a0[5], a1[5];
#pragma unroll
    for (int i = 0; i < 5; i++) { a0[i] = 0.f; a1[i] = 0.f; }

    for (unsigned p = blockIdx.x * PPB + q; p < (unsigned)HW; p += STRIDE) {
        const int lab = __ldg(labbase + p);          // broadcast within quad

        float e[5];
#pragma unroll
        for (int i = 0; i < 4; i++)
            e[i] = __ldg(pbase + (size_t)i * HW + p);   // imm offsets i*2MB
        e[4] = __ldg(p4 + p);                           // dup of e[3] when dead

        float S = 0.f;
#pragma unroll
        for (int i = 0; i < 5; i++) { e[i] = __expf(e[i]); S += e[i]; }
        S = fmaf(-dead, e[4], S);                    // remove duplicate if dead
        // Softmax denominator across the 4-lane quad: two butterflies.
        S += __shfl_xor_sync(~0u, S, 1);
        S += __shfl_xor_sync(~0u, S, 2);
        const float w = __fdividef(15.f, S);

#pragma unroll
        for (int i = 0; i < 5; i++) {
            const int c = c0 + i;                   // unclamped: dead slot c=19
            const float t = e[i] * w;               // 15*p
            float v = t;
            if (c == lab) v = t - 15.f;             // never true for dead slot
            if (t <= 1.f) a0[i] += v;               // cumulative levels
            if (t <= 2.f) a1[i] += v;
            // Rare path (t > 2, ~7.7%): branch-free predicated shared red.
            // addr = cb0 + i*NBINS*4 + min(ceil(t),15)*4  (imm slot offset).
            const unsigned addr = cb0 + (unsigned)(i * NBINS * 4) +
                                  (unsigned)(min(__float2int_ru(t), NBINS) << 2);
            const float thr = (i < 4) ? 2.f : thr4; // compile-time select
            asm volatile(
                "{ .reg .pred p; setp.gt.f32 p, %1, %3;\n\t"
                "  @p red.shared.add.f32 [%0], %2; }"
                :: "r"(addr), "f"(t), "f"(v), "f"(thr));
        }
    }

    // Reduce accumulators over lanes of the same group (bits 2..4 of lane id).
    const int lane = threadIdx.x & 31;
#pragma unroll
    for (int i = 0; i < 5; i++) {
        float x0 = a0[i], x1 = a1[i];
#pragma unroll
        for (int s = 4; s < 32; s <<= 1) {
            x0 += __shfl_xor_sync(~0u, x0, s);
            x1 += __shfl_xor_sync(~0u, x1, s);
        }
        if (lane < 4 && c0 + i < NCLS) {            // lane == its own group id
            atomicAdd(&s_hist[(c0 + i) * NBINS + 0], x0);
            atomicAdd(&s_hist[(c0 + i) * NBINS + 1], x1 - x0);
        }
    }
    __syncthreads();

    for (int i = threadIdx.x; i < NCELLS; i += NT) {
        const float v = s_hist[i];
        if (v != 0.f) atomicAdd(&g_hist[i], v);
    }

    // Completion protocol; last block finalizes and restores invariants.
    __threadfence();
    __syncthreads();
    if (threadIdx.x == 0) {
        const unsigned r = atomicInc(&g_count, GRIDB - 1);   // wraps back to 0
        s_last = (r == GRIDB - 1);
    }
    __syncthreads();

    if (s_last && threadIdx.x < 32) {
        __threadfence();
        double local = 0.0;
        for (int i = lane; i < NCELLS; i += 32) {
            local += fabs((double)g_hist[i]);
            g_hist[i] = 0.f;
        }
#pragma unroll
        for (int s = 16; s > 0; s >>= 1)
            local += __shfl_xor_sync(~0u, local, s);
        if (lane == 0)
            out[0] = (float)(local / (15.0 * (double)NCLS * (double)NPIX));
    }
}

extern "C" void kernel_launch(void* const* d_in, const int* in_sizes, int n_in,
                              void* d_out, int out_size) {
    const float* logits;
    const int*   labels;
    if (in_sizes[0] == NPIX) {               // defensive order detection by size
        labels = (const int*)d_in[0];
        logits = (const float*)d_in[1];
    } else {
        logits = (const float*)d_in[0];
        labels = (const int*)d_in[1];
    }
    float* out = (float*)d_out;

    dim3 grid(GX, 4);
    ece_fused<<<grid, NT>>>(logits, labels, out);
}